// round 14
// baseline (speedup 1.0000x reference)
#include <cuda_runtime.h>
#include <cuda_bf16.h>
#include <math.h>
#include <float.h>
#include <stdint.h>

// Problem constants
#define NPAIR 2048           // B*A
#define HD 128               // H
#define NTOK 256             // N
#define KTOP 16
#define NSPLIT1 17           // 2176 / 128

// Scratch (device globals; no allocations allowed)
__device__ float g_M[HD * HD];                    // norm * Wq @ Wk^T
__device__ float g_qeff[NPAIR * HD];
__device__ float g_X[NPAIR * 2 * HD];             // [vs | s_ve]
__device__ int   g_idx[NPAIR * KTOP];             // top-16 indices
__device__ float g_part[(size_t)NSPLIT1 * NPAIR * HD];  // v_C split-K partials
// bf16 hi/lo weight splits
__device__ __nv_bfloat16 g_Wfh[HD * 2176];
__device__ __nv_bfloat16 g_Wfl[HD * 2176];
__device__ __nv_bfloat16 g_Wmh[HD * 256];
__device__ __nv_bfloat16 g_Wml[HD * 256];

#define NWF (HD * 2176)

__device__ __forceinline__ uint32_t smem_u32(const void* p) {
    uint32_t a;
    asm("{ .reg .u64 t; cvta.to.shared.u64 t, %1; cvt.u32.u64 %0, t; }" : "=r"(a) : "l"(p));
    return a;
}
#define MBAR_INIT(mb, c) asm volatile("mbarrier.init.shared.b64 [%0], %1;" \
    :: "r"((uint32_t)(mb)), "r"((uint32_t)(c)) : "memory")
#define MBAR_WAIT(mb, par) do { \
    uint32_t _mb = (uint32_t)(mb), _pa = (uint32_t)(par), _dn; \
    asm volatile("{\n\t.reg .pred p;\n\t" \
        "mbarrier.try_wait.parity.acquire.cta.shared::cta.b64 p, [%1], %2;\n\t" \
        "selp.b32 %0, 1, 0, p;\n\t}" : "=r"(_dn) : "r"(_mb), "r"(_pa) : "memory"); \
    if (!_dn) { \
        asm volatile("{\n\t.reg .pred P1;\n\tWL_%=:\n\t" \
            "mbarrier.try_wait.parity.acquire.cta.shared::cta.b64 P1, [%0], %1, 0x989680;\n\t" \
            "@P1 bra.uni WD_%=;\n\tbra.uni WL_%=;\n\tWD_%=:\n\t}" \
            :: "r"(_mb), "r"(_pa) : "memory"); \
    } } while (0)

__device__ __forceinline__ void bf16_split(float w, __nv_bfloat16& h, __nv_bfloat16& l) {
    h = __float2bfloat16_rn(w);
    l = __float2bfloat16_rn(w - __bfloat162float(h));
}

// ---------------------------------------------------------------------------
// Kernel 0: fused prep — g_M, Wmod (direct to bf16 hi/lo), Wfwd hi/lo split.
// grid 2432, block 128.
// ---------------------------------------------------------------------------
__global__ void prep2_kernel(const float* __restrict__ Wq, const float* __restrict__ Wk,
                             const float* __restrict__ Wv, const float* __restrict__ Wmot,
                             const float* __restrict__ Wfwd) {
    __shared__ float srow[HD];
    int bx = blockIdx.x;
    int t = threadIdx.x;

    if (bx < 128) {
        srow[t] = Wk[bx * HD + t];
        __syncthreads();
        const float* wq = Wq + t * HD;
        float acc = 0.f;
#pragma unroll 8
        for (int j = 0; j < HD; j++) acc += wq[j] * srow[j];
        g_M[t * HD + bx] = acc * 0.08838834764831845f;  // 1/sqrt(128)
    } else if (bx < 256) {
        int col = bx - 128;
        srow[t] = Wmot[col * 2 * HD + HD + t];
        __syncthreads();
        bf16_split(Wmot[col * 2 * HD + t], g_Wmh[col * 2 * HD + t], g_Wml[col * 2 * HD + t]);
        const float* wv = Wv + t * HD;
        float acc = 0.f;
#pragma unroll 8
        for (int h = 0; h < HD; h++) acc += wv[h] * srow[h];
        bf16_split(acc, g_Wmh[col * 2 * HD + HD + t], g_Wml[col * 2 * HD + HD + t]);
    } else {
        int i = (bx - 256) * 128 + t;
        if (i < NWF) bf16_split(Wfwd[i], g_Wfh[i], g_Wfl[i]);
    }
}

// ---------------------------------------------------------------------------
// Kernel 1: qeff[p][t] = sum_i vs[p][i] * g_M[i][t].
// grid 512, block 128; 4 pairs per block, unroll 8.
// ---------------------------------------------------------------------------
__global__ void qeff_kernel(const float* __restrict__ vs) {
    __shared__ float svs[4 * HD];
    int t = threadIdx.x;
    int base = blockIdx.x * 4;
    for (int k = t; k < 4 * HD; k += 128) svs[k] = vs[base * HD + k];
    __syncthreads();
    float acc[4];
#pragma unroll
    for (int p = 0; p < 4; p++) acc[p] = 0.f;
#pragma unroll 8
    for (int i = 0; i < HD; i++) {
        float m = __ldg(&g_M[i * HD + t]);
#pragma unroll
        for (int p = 0; p < 4; p++) acc[p] += svs[p * HD + i] * m;
    }
#pragma unroll
    for (int p = 0; p < 4; p++) g_qeff[(base + p) * HD + t] = acc[p];
}

// ---------------------------------------------------------------------------
// Kernel 2: one-pass attention, cp.async.bulk pipeline. (R11, passing)
// grid 2048, block 256, dyn smem 48 KB (3 x 16KB chunks of 32 rows).
// ---------------------------------------------------------------------------
__global__ __launch_bounds__(256, 4) void attn_kernel(const float* __restrict__ vs,
                                                      const float* __restrict__ ve,
                                                      const int* __restrict__ ved) {
    extern __shared__ float sve[];      // [3][4096] floats = 48 KB
    __shared__ float sc[NTOK];          // exp(compat)
    __shared__ float lred[8];
    __shared__ int sdead[NTOK];
    __shared__ uint64_t mbar[3];

    int tid = threadIdx.x;
    int lane = tid & 31, wid = tid >> 5;
    int p = blockIdx.x;

    sdead[tid] = ved[p * NTOK + tid];
    float4 q = *(const float4*)(g_qeff + p * HD + lane * 4);
    const char* src = (const char*)(ve + (size_t)p * NTOK * HD);
    uint32_t sbase = smem_u32(sve);

    if (tid < 3) MBAR_INIT(smem_u32(&mbar[tid]), 1);
    __syncthreads();

    auto issue = [&](int c) {
        int b = c % 3;
        uint32_t mb = smem_u32(&mbar[b]);
        asm volatile("mbarrier.arrive.expect_tx.shared.b64 _, [%0], %1;"
                     :: "r"(mb), "r"(16384u) : "memory");
        asm volatile("cp.async.bulk.shared::cta.global.mbarrier::complete_tx::bytes "
                     "[%0], [%1], %2, [%3];"
                     :: "r"(sbase + (uint32_t)b * 16384u), "l"(src + (size_t)c * 16384),
                        "r"(16384u), "r"(mb) : "memory");
    };
    if (tid == 0) { issue(0); issue(1); issue(2); }

    float l = 0.f;
    float4 acc = make_float4(0.f, 0.f, 0.f, 0.f);

    for (int c = 0; c < 8; c++) {
        int b = c % 3;
        MBAR_WAIT(smem_u32(&mbar[b]), (c / 3) & 1);

        const float* bb = sve + b * 4096 + (wid * 4) * 128 + lane * 4;
        float4 a0 = *(const float4*)(bb);
        float4 a1 = *(const float4*)(bb + 128);
        float4 a2 = *(const float4*)(bb + 256);
        float4 a3 = *(const float4*)(bb + 384);

        float c0 = a0.x * q.x + a0.y * q.y + a0.z * q.z + a0.w * q.w;
        float c1 = a1.x * q.x + a1.y * q.y + a1.z * q.z + a1.w * q.w;
        float c2 = a2.x * q.x + a2.y * q.y + a2.z * q.z + a2.w * q.w;
        float c3 = a3.x * q.x + a3.y * q.y + a3.z * q.z + a3.w * q.w;
#pragma unroll
        for (int o = 16; o > 0; o >>= 1) {
            c0 += __shfl_xor_sync(0xffffffffu, c0, o);
            c1 += __shfl_xor_sync(0xffffffffu, c1, o);
            c2 += __shfl_xor_sync(0xffffffffu, c2, o);
            c3 += __shfl_xor_sync(0xffffffffu, c3, o);
        }
        int r0 = c * 32 + wid * 4;
        float e0 = sdead[r0]     ? 0.f : expf(c0);
        float e1 = sdead[r0 + 1] ? 0.f : expf(c1);
        float e2 = sdead[r0 + 2] ? 0.f : expf(c2);
        float e3 = sdead[r0 + 3] ? 0.f : expf(c3);
        if (lane == 0) {
            sc[r0] = e0; sc[r0 + 1] = e1; sc[r0 + 2] = e2; sc[r0 + 3] = e3;
        }
        l += (e0 + e1) + (e2 + e3);
        acc.x += e0 * a0.x + e1 * a1.x + e2 * a2.x + e3 * a3.x;
        acc.y += e0 * a0.y + e1 * a1.y + e2 * a2.y + e3 * a3.y;
        acc.z += e0 * a0.z + e1 * a1.z + e2 * a2.z + e3 * a3.z;
        acc.w += e0 * a0.w + e1 * a1.w + e2 * a2.w + e3 * a3.w;

        __syncthreads();                  // all readers done with buffer b
        if (c < 5 && tid == 0) issue(c + 3);
    }

    // pipeline buffers dead: alias accumulator area into dynamic smem
    float* accsh = sve;                  // [8][132]
    if (lane == 0) lred[wid] = l;
    *(float4*)(accsh + wid * 132 + lane * 4) = acc;
    __syncthreads();

    float Lt = lred[0];
#pragma unroll
    for (int w = 1; w < 8; w++) Lt += lred[w];

    if (tid < HD) {
        float ssum = 0.f;
#pragma unroll
        for (int w = 0; w < 8; w++) ssum += accsh[w * 132 + tid];
        g_X[p * 2 * HD + tid] = vs[p * HD + tid];
        g_X[p * 2 * HD + HD + tid] = (Lt > 0.f) ? ssum / Lt : 0.f;
    }
    __syncthreads();

    // top-16 on unnormalized e (monotone with score): stable desc, index asc.
    if (wid == 0) {
        float val[8];
#pragma unroll
        for (int j = 0; j < 8; j++) val[j] = sc[lane + (j << 5)];
        for (int k = 0; k < KTOP; k++) {
            float bv = val[0];
            int bj = 0;
#pragma unroll
            for (int j = 1; j < 8; j++)
                if (val[j] > bv) { bv = val[j]; bj = j; }  // strict > keeps lowest index
            int bi = (bj << 5) + lane;
#pragma unroll
            for (int o = 16; o > 0; o >>= 1) {
                float ov = __shfl_xor_sync(0xffffffffu, bv, o);
                int oi = __shfl_xor_sync(0xffffffffu, bi, o);
                if (ov > bv || (ov == bv && oi < bi)) { bv = ov; bi = oi; }
            }
            if (lane == 0) g_idx[p * KTOP + k] = bi;
            if ((bi & 31) == lane) val[bi >> 5] = -1.f;  // e >= 0
        }
    }
}

// ---------------------------------------------------------------------------
// Kernel 3: bf16 tensor-core GEMM (mma.sync m16n8k16), hi/lo fp32 recon.
// grid (16, 18): s<17 -> v_C split s (2 k-slices, partial -> g_part[s]);
//                s==17 -> v_M FULL K=256 (4 k-slices) -> out directly
//                         with bias + relu (no partials, no fence).
// W tiles via cp.async (overlap with A fetch+convert). 288 CTAs = 1 wave.
// ---------------------------------------------------------------------------
__global__ __launch_bounds__(256, 2) void gemm_mma_kernel(const float* __restrict__ ve,
                                                          const float* __restrict__ vs,
                                                          const float* __restrict__ bmot,
                                                          float* __restrict__ out) {
    extern __shared__ char smg[];
    const uint32_t OFF_AH = 0, OFF_AL = 18432, OFF_WH = 36864, OFF_WL = 55296;
    uint32_t sb = smem_u32(smg);

    int tid = threadIdx.x;
    int lane = tid & 31, wid = tid >> 5;
    int br = blockIdx.x * 128;
    int s = blockIdx.y;
    int mode1 = (s == NSPLIT1);
    int nk = mode1 ? 4 : 2;
    int k0 = mode1 ? 0 : s * 128;
    int Kst = mode1 ? 256 : 2176;
    const __nv_bfloat16* Wh = mode1 ? g_Wmh : g_Wfh;
    const __nv_bfloat16* Wl = mode1 ? g_Wml : g_Wfl;

    int lr = tid >> 1, lh = tid & 1;
    const float* aptr;
    {
        int p = br + lr;
        if (!mode1) {
            aptr = (s == 0) ? vs + (size_t)p * HD
                            : ve + ((size_t)p * NTOK + g_idx[p * KTOP + s - 1]) * HD;
        } else {
            aptr = g_X + (size_t)p * 2 * HD;
        }
    }
    const __nv_bfloat16* whp = Wh + (size_t)lr * Kst + k0;
    const __nv_bfloat16* wlp = Wl + (size_t)lr * Kst + k0;

    int wm = wid & 3;
    int wn = wid >> 2;
    uint32_t arow = (lane & 7) + ((lane >> 3) & 1) * 8;
    uint32_t akb  = (lane >> 4) * 16;
    uint32_t nrow = ((lane >> 4) & 1) * 8 + (lane & 7);
    uint32_t bkb  = ((lane >> 3) & 1) * 16;

    float acc[2][8][4];
#pragma unroll
    for (int i = 0; i < 2; i++)
#pragma unroll
        for (int j = 0; j < 8; j++)
#pragma unroll
            for (int v = 0; v < 4; v++) acc[i][j][v] = 0.f;

    const uint32_t aoff[3] = { OFF_AH, OFF_AH, OFF_AL };
    const uint32_t woff[3] = { OFF_WH, OFF_WL, OFF_WH };

    for (int kk = 0; kk < nk; kk++) {
        {
            // Issue W tile fills first via cp.async (overlaps with A below)
            uint32_t dWh = sb + OFF_WH + lr * 144 + lh * 64;
            uint32_t dWl = sb + OFF_WL + lr * 144 + lh * 64;
            const char* gWh = (const char*)(whp + kk * 64 + lh * 32);
            const char* gWl = (const char*)(wlp + kk * 64 + lh * 32);
#pragma unroll
            for (int j = 0; j < 4; j++) {
                asm volatile("cp.async.cg.shared.global [%0], [%1], 16;"
                             :: "r"(dWh + j * 16), "l"(gWh + j * 16));
                asm volatile("cp.async.cg.shared.global [%0], [%1], 16;"
                             :: "r"(dWl + j * 16), "l"(gWl + j * 16));
            }
            asm volatile("cp.async.commit_group;" ::: "memory");

            // A: 32 fp32 -> bf16 hi/lo
            const float4* a4 = (const float4*)(aptr + kk * 64 + lh * 32);
            char* dAh = smg + OFF_AH + lr * 144 + lh * 64;
            char* dAl = smg + OFF_AL + lr * 144 + lh * 64;
#pragma unroll
            for (int j = 0; j < 8; j++) {
                float4 f = a4[j];
                __nv_bfloat162 h0 = __floats2bfloat162_rn(f.x, f.y);
                __nv_bfloat162 h1 = __floats2bfloat162_rn(f.z, f.w);
                float2 r0 = __bfloat1622float2(h0);
                float2 r1 = __bfloat1622float2(h1);
                __nv_bfloat162 l0 = __floats2bfloat162_rn(f.x - r0.x, f.y - r0.y);
                __nv_bfloat162 l1 = __floats2bfloat162_rn(f.z - r1.x, f.w - r1.y);
                *(uint2*)(dAh + j * 8) = make_uint2(*(uint32_t*)&h0, *(uint32_t*)&h1);
                *(uint2*)(dAl + j * 8) = make_uint2(*(uint32_t*)&l0, *(uint32_t*)&l1);
            }
            asm volatile("cp.async.wait_group 0;" ::: "memory");
        }
        __syncthreads();

#pragma unroll
        for (int pass = 0; pass < 3; pass++) {
            uint32_t Ab = sb + aoff[pass] + (wm * 32 + arow) * 144 + akb;
            uint32_t Wb = sb + woff[pass] + (wn * 64 + nrow) * 144 + bkb;
#pragma unroll
            for (int ks = 0; ks < 4; ks++) {
                uint32_t a[2][4];
#pragma unroll
                for (int mt = 0; mt < 2; mt++) {
                    uint32_t ad = Ab + mt * 16 * 144 + ks * 32;
                    asm volatile("ldmatrix.sync.aligned.m8n8.x4.shared.b16 {%0,%1,%2,%3}, [%4];"
                                 : "=r"(a[mt][0]), "=r"(a[mt][1]), "=r"(a[mt][2]), "=r"(a[mt][3])
                                 : "r"(ad));
                }
                uint32_t b[4][4];
#pragma unroll
                for (int g = 0; g < 4; g++) {
                    uint32_t bd = Wb + g * 16 * 144 + ks * 32;
                    asm volatile("ldmatrix.sync.aligned.m8n8.x4.shared.b16 {%0,%1,%2,%3}, [%4];"
                                 : "=r"(b[g][0]), "=r"(b[g][1]), "=r"(b[g][2]), "=r"(b[g][3])
                                 : "r"(bd));
                }
#pragma unroll
                for (int mt = 0; mt < 2; mt++)
#pragma unroll
                    for (int nt = 0; nt < 8; nt++) {
                        uint32_t b0 = b[nt >> 1][(nt & 1) * 2];
                        uint32_t b1 = b[nt >> 1][(nt & 1) * 2 + 1];
                        asm volatile(
                            "mma.sync.aligned.m16n8k16.row.col.f32.bf16.bf16.f32 "
                            "{%0,%1,%2,%3}, {%4,%5,%6,%7}, {%8,%9}, {%0,%1,%2,%3};"
                            : "+f"(acc[mt][nt][0]), "+f"(acc[mt][nt][1]),
                              "+f"(acc[mt][nt][2]), "+f"(acc[mt][nt][3])
                            : "r"(a[mt][0]), "r"(a[mt][1]), "r"(a[mt][2]), "r"(a[mt][3]),
                              "r"(b0), "r"(b1));
                    }
            }
        }
        __syncthreads();
    }

    if (mode1) {
        // v_M: full-K result -> out directly with bias + relu
        float* o2 = out + (size_t)NPAIR * HD + (size_t)br * HD;
#pragma unroll
        for (int mt = 0; mt < 2; mt++) {
            int row0 = wm * 32 + mt * 16 + (lane >> 2);
#pragma unroll
            for (int nt = 0; nt < 8; nt++) {
                int col = wn * 64 + nt * 8 + (lane & 3) * 2;
                float b0 = bmot[col], b1 = bmot[col + 1];
                *(float2*)(o2 + (size_t)row0 * HD + col) =
                    make_float2(fmaxf(acc[mt][nt][0] + b0, 0.f),
                                fmaxf(acc[mt][nt][1] + b1, 0.f));
                *(float2*)(o2 + (size_t)(row0 + 8) * HD + col) =
                    make_float2(fmaxf(acc[mt][nt][2] + b0, 0.f),
                                fmaxf(acc[mt][nt][3] + b1, 0.f));
            }
        }
        return;
    }

    float* pout = g_part + (size_t)s * NPAIR * HD + (size_t)br * HD;
#pragma unroll
    for (int mt = 0; mt < 2; mt++) {
        int row0 = wm * 32 + mt * 16 + (lane >> 2);
#pragma unroll
        for (int nt = 0; nt < 8; nt++) {
            int col = wn * 64 + nt * 8 + (lane & 3) * 2;
            *(float2*)(pout + (size_t)row0 * HD + col) =
                make_float2(acc[mt][nt][0], acc[mt][nt][1]);
            *(float2*)(pout + (size_t)(row0 + 8) * HD + col) =
                make_float2(acc[mt][nt][2], acc[mt][nt][3]);
        }
    }
}

// Reduce v_C: sum 17 split slots + bias + relu. grid 1024, block 256.
__global__ void reduce_relu_kernel(const float* __restrict__ bfwd,
                                   float* __restrict__ out) {
    int idx = blockIdx.x * 256 + threadIdx.x;
    float s = 0.f;
#pragma unroll
    for (int sp = 0; sp < NSPLIT1; sp++) s += g_part[(size_t)sp * NPAIR * HD + idx];
    out[idx] = fmaxf(s + bfwd[idx & (HD - 1)], 0.f);
}

// ---------------------------------------------------------------------------
extern "C" void kernel_launch(void* const* d_in, const int* in_sizes, int n_in,
                              void* d_out, int out_size) {
    const float* vs   = (const float*)d_in[0];
    const float* ve   = (const float*)d_in[1];
    const int*   ved  = (const int*)d_in[2];
    const float* Wq   = (const float*)d_in[3];
    const float* Wk   = (const float*)d_in[4];
    const float* Wv   = (const float*)d_in[5];
    const float* Wmot = (const float*)d_in[6];
    const float* bmot = (const float*)d_in[7];
    const float* Wfwd = (const float*)d_in[8];
    const float* bfwd = (const float*)d_in[9];
    float* out = (float*)d_out;  // [v_C_final (2048*128) | v_M_final (2048*128)]

    const int SMEM_A  = 3 * 4096 * 4;   // 48 KB attn pipeline
    const int SMEM_MM = 73728;          // 4 x 18432 B bf16 tiles
    cudaFuncSetAttribute(attn_kernel, cudaFuncAttributeMaxDynamicSharedMemorySize, SMEM_A);
    cudaFuncSetAttribute(gemm_mma_kernel, cudaFuncAttributeMaxDynamicSharedMemorySize, SMEM_MM);

    // 5 launches
    prep2_kernel<<<256 + (NWF + 127) / 128, 128>>>(Wq, Wk, Wv, Wmot, Wfwd);
    qeff_kernel<<<512, 128>>>(vs);
    attn_kernel<<<NPAIR, 256, SMEM_A>>>(vs, ve, ved);
    gemm_mma_kernel<<<dim3(NPAIR / 128, NSPLIT1 + 1), 256, SMEM_MM>>>(ve, vs, bmot, out);
    reduce_relu_kernel<<<1024, 256>>>(bfwd, out);
}

// round 15
// speedup vs baseline: 1.1125x; 1.1125x over previous
#include <cuda_runtime.h>
#include <cuda_bf16.h>
#include <math.h>
#include <float.h>
#include <stdint.h>

// Problem constants
#define NPAIR 2048           // B*A
#define HD 128               // H
#define NTOK 256             // N
#define KTOP 16
#define NSPLIT1 17           // 2176 / 128
#define NSLOTS 19            // 17 (gemm1) + 2 (gemm2)

// Scratch (device globals; no allocations allowed)
__device__ float g_M[HD * HD];                    // norm * Wq @ Wk^T
__device__ float g_Wmod[HD * 2 * HD];             // [Wmot(:, :128) | Wv @ Wmot(:,128:)^T]
__device__ float g_qeff[NPAIR * HD];
__device__ float g_X[NPAIR * 2 * HD];             // [vs | s_ve]
__device__ int   g_idx[NPAIR * KTOP];             // top-16 indices
__device__ float g_part[(size_t)NSLOTS * NPAIR * HD];  // split-K partials
// bf16 hi/lo weight splits
__device__ __nv_bfloat16 g_Wfh[HD * 2176];
__device__ __nv_bfloat16 g_Wfl[HD * 2176];
__device__ __nv_bfloat16 g_Wmh[HD * 256];
__device__ __nv_bfloat16 g_Wml[HD * 256];

__device__ __forceinline__ uint32_t smem_u32(const void* p) {
    uint32_t a;
    asm("{ .reg .u64 t; cvta.to.shared.u64 t, %1; cvt.u32.u64 %0, t; }" : "=r"(a) : "l"(p));
    return a;
}
#define MBAR_INIT(mb, c) asm volatile("mbarrier.init.shared.b64 [%0], %1;" \
    :: "r"((uint32_t)(mb)), "r"((uint32_t)(c)) : "memory")
#define MBAR_WAIT(mb, par) do { \
    uint32_t _mb = (uint32_t)(mb), _pa = (uint32_t)(par), _dn; \
    asm volatile("{\n\t.reg .pred p;\n\t" \
        "mbarrier.try_wait.parity.acquire.cta.shared::cta.b64 p, [%1], %2;\n\t" \
        "selp.b32 %0, 1, 0, p;\n\t}" : "=r"(_dn) : "r"(_mb), "r"(_pa) : "memory"); \
    if (!_dn) { \
        asm volatile("{\n\t.reg .pred P1;\n\tWL_%=:\n\t" \
            "mbarrier.try_wait.parity.acquire.cta.shared::cta.b64 P1, [%0], %1, 0x989680;\n\t" \
            "@P1 bra.uni WD_%=;\n\tbra.uni WL_%=;\n\tWD_%=:\n\t}" \
            :: "r"(_mb), "r"(_pa) : "memory"); \
    } } while (0)

// ---------------------------------------------------------------------------
// Kernel 0: build fused weight matrices. grid (128, 2), block 128
// ---------------------------------------------------------------------------
__global__ void prep_kernel(const float* __restrict__ Wq, const float* __restrict__ Wk,
                            const float* __restrict__ Wv, const float* __restrict__ Wmot) {
    __shared__ float srow[HD];
    int col = blockIdx.x;
    int t = threadIdx.x;
    if (blockIdx.y == 0) {
        srow[t] = Wk[col * HD + t];
        __syncthreads();
        const float* wq = Wq + t * HD;
        float acc = 0.f;
#pragma unroll 8
        for (int j = 0; j < HD; j++) acc += wq[j] * srow[j];
        g_M[t * HD + col] = acc * 0.08838834764831845f;  // 1/sqrt(128)
    } else {
        srow[t] = Wmot[col * 2 * HD + HD + t];
        __syncthreads();
        g_Wmod[col * 2 * HD + t] = Wmot[col * 2 * HD + t];
        const float* wv = Wv + t * HD;
        float acc = 0.f;
#pragma unroll 8
        for (int h = 0; h < HD; h++) acc += wv[h] * srow[h];
        g_Wmod[col * 2 * HD + HD + t] = acc;
    }
}

// ---------------------------------------------------------------------------
// Kernel 0b: split weights into bf16 hi/lo. Runs after prep (needs g_Wmod).
// ---------------------------------------------------------------------------
#define NWF (HD * 2176)
#define NWM (HD * 256)
__global__ void wconv_kernel(const float* __restrict__ Wfwd) {
    int i = blockIdx.x * 256 + threadIdx.x;
    if (i < NWF) {
        float w = Wfwd[i];
        __nv_bfloat16 h = __float2bfloat16_rn(w);
        g_Wfh[i] = h;
        g_Wfl[i] = __float2bfloat16_rn(w - __bfloat162float(h));
    } else if (i < NWF + NWM) {
        int j = i - NWF;
        float w = g_Wmod[j];
        __nv_bfloat16 h = __float2bfloat16_rn(w);
        g_Wmh[j] = h;
        g_Wml[j] = __float2bfloat16_rn(w - __bfloat162float(h));
    }
}

// ---------------------------------------------------------------------------
// Kernel 1: qeff[p][t] = sum_i vs[p][i] * g_M[i][t].
// grid 256, block 128; 8 pairs per block.
// ---------------------------------------------------------------------------
__global__ void qeff_kernel(const float* __restrict__ vs) {
    __shared__ float svs[8 * HD];
    int t = threadIdx.x;
    int base = blockIdx.x * 8;
    for (int k = t; k < 8 * HD; k += 128) svs[k] = vs[base * HD + k];
    __syncthreads();
    float acc[8];
#pragma unroll
    for (int p = 0; p < 8; p++) acc[p] = 0.f;
#pragma unroll 4
    for (int i = 0; i < HD; i++) {
        float m = g_M[i * HD + t];
#pragma unroll
        for (int p = 0; p < 8; p++) acc[p] += svs[p * HD + i] * m;
    }
#pragma unroll
    for (int p = 0; p < 8; p++) g_qeff[(base + p) * HD + t] = acc[p];
}

// ---------------------------------------------------------------------------
// Kernel 2: one-pass attention, cp.async.bulk pipeline. (R11, passing)
// grid 2048, block 256, dyn smem 48 KB (3 x 16KB chunks of 32 rows).
// ---------------------------------------------------------------------------
__global__ __launch_bounds__(256, 4) void attn_kernel(const float* __restrict__ vs,
                                                      const float* __restrict__ ve,
                                                      const int* __restrict__ ved) {
    extern __shared__ float sve[];      // [3][4096] floats = 48 KB
    __shared__ float sc[NTOK];          // exp(compat)
    __shared__ float lred[8];
    __shared__ int sdead[NTOK];
    __shared__ uint64_t mbar[3];

    int tid = threadIdx.x;
    int lane = tid & 31, wid = tid >> 5;
    int p = blockIdx.x;

    sdead[tid] = ved[p * NTOK + tid];
    float4 q = *(const float4*)(g_qeff + p * HD + lane * 4);
    const char* src = (const char*)(ve + (size_t)p * NTOK * HD);
    uint32_t sbase = smem_u32(sve);

    if (tid < 3) MBAR_INIT(smem_u32(&mbar[tid]), 1);
    __syncthreads();

    auto issue = [&](int c) {
        int b = c % 3;
        uint32_t mb = smem_u32(&mbar[b]);
        asm volatile("mbarrier.arrive.expect_tx.shared.b64 _, [%0], %1;"
                     :: "r"(mb), "r"(16384u) : "memory");
        asm volatile("cp.async.bulk.shared::cta.global.mbarrier::complete_tx::bytes "
                     "[%0], [%1], %2, [%3];"
                     :: "r"(sbase + (uint32_t)b * 16384u), "l"(src + (size_t)c * 16384),
                        "r"(16384u), "r"(mb) : "memory");
    };
    if (tid == 0) { issue(0); issue(1); issue(2); }

    float l = 0.f;
    float4 acc = make_float4(0.f, 0.f, 0.f, 0.f);

    for (int c = 0; c < 8; c++) {
        int b = c % 3;
        MBAR_WAIT(smem_u32(&mbar[b]), (c / 3) & 1);

        const float* bb = sve + b * 4096 + (wid * 4) * 128 + lane * 4;
        float4 a0 = *(const float4*)(bb);
        float4 a1 = *(const float4*)(bb + 128);
        float4 a2 = *(const float4*)(bb + 256);
        float4 a3 = *(const float4*)(bb + 384);

        float c0 = a0.x * q.x + a0.y * q.y + a0.z * q.z + a0.w * q.w;
        float c1 = a1.x * q.x + a1.y * q.y + a1.z * q.z + a1.w * q.w;
        float c2 = a2.x * q.x + a2.y * q.y + a2.z * q.z + a2.w * q.w;
        float c3 = a3.x * q.x + a3.y * q.y + a3.z * q.z + a3.w * q.w;
#pragma unroll
        for (int o = 16; o > 0; o >>= 1) {
            c0 += __shfl_xor_sync(0xffffffffu, c0, o);
            c1 += __shfl_xor_sync(0xffffffffu, c1, o);
            c2 += __shfl_xor_sync(0xffffffffu, c2, o);
            c3 += __shfl_xor_sync(0xffffffffu, c3, o);
        }
        int r0 = c * 32 + wid * 4;
        float e0 = sdead[r0]     ? 0.f : expf(c0);
        float e1 = sdead[r0 + 1] ? 0.f : expf(c1);
        float e2 = sdead[r0 + 2] ? 0.f : expf(c2);
        float e3 = sdead[r0 + 3] ? 0.f : expf(c3);
        if (lane == 0) {
            sc[r0] = e0; sc[r0 + 1] = e1; sc[r0 + 2] = e2; sc[r0 + 3] = e3;
        }
        l += (e0 + e1) + (e2 + e3);
        acc.x += e0 * a0.x + e1 * a1.x + e2 * a2.x + e3 * a3.x;
        acc.y += e0 * a0.y + e1 * a1.y + e2 * a2.y + e3 * a3.y;
        acc.z += e0 * a0.z + e1 * a1.z + e2 * a2.z + e3 * a3.z;
        acc.w += e0 * a0.w + e1 * a1.w + e2 * a2.w + e3 * a3.w;

        __syncthreads();                  // all readers done with buffer b
        if (c < 5 && tid == 0) issue(c + 3);
    }

    // pipeline buffers dead: alias accumulator area into dynamic smem
    float* accsh = sve;                  // [8][132]
    if (lane == 0) lred[wid] = l;
    *(float4*)(accsh + wid * 132 + lane * 4) = acc;
    __syncthreads();

    float Lt = lred[0];
#pragma unroll
    for (int w = 1; w < 8; w++) Lt += lred[w];

    if (tid < HD) {
        float ssum = 0.f;
#pragma unroll
        for (int w = 0; w < 8; w++) ssum += accsh[w * 132 + tid];
        g_X[p * 2 * HD + tid] = vs[p * HD + tid];
        g_X[p * 2 * HD + HD + tid] = (Lt > 0.f) ? ssum / Lt : 0.f;
    }
    __syncthreads();

    // top-16 on unnormalized e (monotone with score): stable desc, index asc.
    if (wid == 0) {
        float val[8];
#pragma unroll
        for (int j = 0; j < 8; j++) val[j] = sc[lane + (j << 5)];
        for (int k = 0; k < KTOP; k++) {
            float bv = val[0];
            int bj = 0;
#pragma unroll
            for (int j = 1; j < 8; j++)
                if (val[j] > bv) { bv = val[j]; bj = j; }  // strict > keeps lowest index
            int bi = (bj << 5) + lane;
#pragma unroll
            for (int o = 16; o > 0; o >>= 1) {
                float ov = __shfl_xor_sync(0xffffffffu, bv, o);
                int oi = __shfl_xor_sync(0xffffffffu, bi, o);
                if (ov > bv || (ov == bv && oi < bi)) { bv = ov; bi = oi; }
            }
            if (lane == 0) g_idx[p * KTOP + k] = bi;
            if ((bi & 31) == lane) val[bi >> 5] = -1.f;  // e >= 0
        }
    }
}

// ---------------------------------------------------------------------------
// Kernel 3: bf16 tensor-core GEMM (mma.sync m16n8k16), hi/lo fp32 recon.
// grid (16, 19): s<17 -> v_C split s; s>=17 -> v_M split s-17. Uniform work.
// W tiles via cp.async (overlaps with A fetch+convert).
// CTA tile 128x128x128 as two 64-wide k-slices. Partials -> g_part[s].
// ---------------------------------------------------------------------------
__global__ __launch_bounds__(256, 2) void gemm_mma_kernel(const float* __restrict__ ve,
                                                          const float* __restrict__ vs) {
    extern __shared__ char smg[];
    const uint32_t OFF_AH = 0, OFF_AL = 18432, OFF_WH = 36864, OFF_WL = 55296;
    uint32_t sb = smem_u32(smg);

    int tid = threadIdx.x;
    int lane = tid & 31, wid = tid >> 5;
    int br = blockIdx.x * 128;
    int s = blockIdx.y;
    int mode1 = (s >= NSPLIT1);
    int k0 = (mode1 ? (s - NSPLIT1) : s) * 128;
    int Kst = mode1 ? 256 : 2176;
    const __nv_bfloat16* Wh = mode1 ? g_Wmh : g_Wfh;
    const __nv_bfloat16* Wl = mode1 ? g_Wml : g_Wfl;

    int lr = tid >> 1, lh = tid & 1;
    const float* aptr;
    {
        int p = br + lr;
        if (!mode1) {
            aptr = (s == 0) ? vs + (size_t)p * HD
                            : ve + ((size_t)p * NTOK + g_idx[p * KTOP + s - 1]) * HD;
        } else {
            aptr = g_X + (size_t)p * 2 * HD + k0;
        }
    }
    const __nv_bfloat16* whp = Wh + (size_t)lr * Kst + k0;
    const __nv_bfloat16* wlp = Wl + (size_t)lr * Kst + k0;

    int wm = wid & 3;
    int wn = wid >> 2;
    uint32_t arow = (lane & 7) + ((lane >> 3) & 1) * 8;
    uint32_t akb  = (lane >> 4) * 16;
    uint32_t nrow = ((lane >> 4) & 1) * 8 + (lane & 7);
    uint32_t bkb  = ((lane >> 3) & 1) * 16;

    float acc[2][8][4];
#pragma unroll
    for (int i = 0; i < 2; i++)
#pragma unroll
        for (int j = 0; j < 8; j++)
#pragma unroll
            for (int v = 0; v < 4; v++) acc[i][j][v] = 0.f;

    const uint32_t aoff[3] = { OFF_AH, OFF_AH, OFF_AL };
    const uint32_t woff[3] = { OFF_WH, OFF_WL, OFF_WH };

    for (int kk = 0; kk < 2; kk++) {
        {
            // Issue W tile fills first via cp.async (overlaps with A below)
            uint32_t dWh = sb + OFF_WH + lr * 144 + lh * 64;
            uint32_t dWl = sb + OFF_WL + lr * 144 + lh * 64;
            const char* gWh = (const char*)(whp + kk * 64 + lh * 32);
            const char* gWl = (const char*)(wlp + kk * 64 + lh * 32);
#pragma unroll
            for (int j = 0; j < 4; j++) {
                asm volatile("cp.async.cg.shared.global [%0], [%1], 16;"
                             :: "r"(dWh + j * 16), "l"(gWh + j * 16));
                asm volatile("cp.async.cg.shared.global [%0], [%1], 16;"
                             :: "r"(dWl + j * 16), "l"(gWl + j * 16));
            }
            asm volatile("cp.async.commit_group;" ::: "memory");

            // A: 32 fp32 -> bf16 hi/lo
            const float4* a4 = (const float4*)(aptr + kk * 64 + lh * 32);
            char* dAh = smg + OFF_AH + lr * 144 + lh * 64;
            char* dAl = smg + OFF_AL + lr * 144 + lh * 64;
#pragma unroll
            for (int j = 0; j < 8; j++) {
                float4 f = a4[j];
                __nv_bfloat162 h0 = __floats2bfloat162_rn(f.x, f.y);
                __nv_bfloat162 h1 = __floats2bfloat162_rn(f.z, f.w);
                float2 r0 = __bfloat1622float2(h0);
                float2 r1 = __bfloat1622float2(h1);
                __nv_bfloat162 l0 = __floats2bfloat162_rn(f.x - r0.x, f.y - r0.y);
                __nv_bfloat162 l1 = __floats2bfloat162_rn(f.z - r1.x, f.w - r1.y);
                *(uint2*)(dAh + j * 8) = make_uint2(*(uint32_t*)&h0, *(uint32_t*)&h1);
                *(uint2*)(dAl + j * 8) = make_uint2(*(uint32_t*)&l0, *(uint32_t*)&l1);
            }
            asm volatile("cp.async.wait_group 0;" ::: "memory");
        }
        __syncthreads();

#pragma unroll
        for (int pass = 0; pass < 3; pass++) {
            uint32_t Ab = sb + aoff[pass] + (wm * 32 + arow) * 144 + akb;
            uint32_t Wb = sb + woff[pass] + (wn * 64 + nrow) * 144 + bkb;
#pragma unroll
            for (int ks = 0; ks < 4; ks++) {
                uint32_t a[2][4];
#pragma unroll
                for (int mt = 0; mt < 2; mt++) {
                    uint32_t ad = Ab + mt * 16 * 144 + ks * 32;
                    asm volatile("ldmatrix.sync.aligned.m8n8.x4.shared.b16 {%0,%1,%2,%3}, [%4];"
                                 : "=r"(a[mt][0]), "=r"(a[mt][1]), "=r"(a[mt][2]), "=r"(a[mt][3])
                                 : "r"(ad));
                }
                uint32_t b[4][4];
#pragma unroll
                for (int g = 0; g < 4; g++) {
                    uint32_t bd = Wb + g * 16 * 144 + ks * 32;
                    asm volatile("ldmatrix.sync.aligned.m8n8.x4.shared.b16 {%0,%1,%2,%3}, [%4];"
                                 : "=r"(b[g][0]), "=r"(b[g][1]), "=r"(b[g][2]), "=r"(b[g][3])
                                 : "r"(bd));
                }
#pragma unroll
                for (int mt = 0; mt < 2; mt++)
#pragma unroll
                    for (int nt = 0; nt < 8; nt++) {
                        uint32_t b0 = b[nt >> 1][(nt & 1) * 2];
                        uint32_t b1 = b[nt >> 1][(nt & 1) * 2 + 1];
                        asm volatile(
                            "mma.sync.aligned.m16n8k16.row.col.f32.bf16.bf16.f32 "
                            "{%0,%1,%2,%3}, {%4,%5,%6,%7}, {%8,%9}, {%0,%1,%2,%3};"
                            : "+f"(acc[mt][nt][0]), "+f"(acc[mt][nt][1]),
                              "+f"(acc[mt][nt][2]), "+f"(acc[mt][nt][3])
                            : "r"(a[mt][0]), "r"(a[mt][1]), "r"(a[mt][2]), "r"(a[mt][3]),
                              "r"(b0), "r"(b1));
                    }
            }
        }
        __syncthreads();
    }

    float* pout = g_part + (size_t)s * NPAIR * HD + (size_t)br * HD;
#pragma unroll
    for (int mt = 0; mt < 2; mt++) {
        int row0 = wm * 32 + mt * 16 + (lane >> 2);
#pragma unroll
        for (int nt = 0; nt < 8; nt++) {
            int col = wn * 64 + nt * 8 + (lane & 3) * 2;
            *(float2*)(pout + (size_t)row0 * HD + col) =
                make_float2(acc[mt][nt][0], acc[mt][nt][1]);
            *(float2*)(pout + (size_t)(row0 + 8) * HD + col) =
                make_float2(acc[mt][nt][2], acc[mt][nt][3]);
        }
    }
}

// Fused reduce: y==0 -> v_C (17 splits, slots 0..16); y==1 -> v_M (slots 17,18)
__global__ void reduce_relu_kernel(const float* __restrict__ bfwd,
                                   const float* __restrict__ bmot,
                                   float* __restrict__ out) {
    int idx = blockIdx.x * 256 + threadIdx.x;
    if (blockIdx.y == 0) {
        float s = 0.f;
#pragma unroll
        for (int sp = 0; sp < NSPLIT1; sp++) s += g_part[(size_t)sp * NPAIR * HD + idx];
        out[idx] = fmaxf(s + bfwd[idx & (HD - 1)], 0.f);
    } else {
        float s = g_part[(size_t)17 * NPAIR * HD + idx] +
                  g_part[(size_t)18 * NPAIR * HD + idx];
        out[NPAIR * HD + idx] = fmaxf(s + bmot[idx & (HD - 1)], 0.f);
    }
}

// ---------------------------------------------------------------------------
extern "C" void kernel_launch(void* const* d_in, const int* in_sizes, int n_in,
                              void* d_out, int out_size) {
    const float* vs   = (const float*)d_in[0];
    const float* ve   = (const float*)d_in[1];
    const int*   ved  = (const int*)d_in[2];
    const float* Wq   = (const float*)d_in[3];
    const float* Wk   = (const float*)d_in[4];
    const float* Wv   = (const float*)d_in[5];
    const float* Wmot = (const float*)d_in[6];
    const float* bmot = (const float*)d_in[7];
    const float* Wfwd = (const float*)d_in[8];
    const float* bfwd = (const float*)d_in[9];
    float* out = (float*)d_out;  // [v_C_final (2048*128) | v_M_final (2048*128)]

    const int SMEM_A  = 3 * 4096 * 4;   // 48 KB attn pipeline
    const int SMEM_MM = 73728;          // 4 x 18432 B bf16 tiles
    cudaFuncSetAttribute(attn_kernel, cudaFuncAttributeMaxDynamicSharedMemorySize, SMEM_A);
    cudaFuncSetAttribute(gemm_mma_kernel, cudaFuncAttributeMaxDynamicSharedMemorySize, SMEM_MM);

    prep_kernel<<<dim3(128, 2), 128>>>(Wq, Wk, Wv, Wmot);
    wconv_kernel<<<(NWF + NWM + 255) / 256, 256>>>(Wfwd);
    qeff_kernel<<<256, 128>>>(vs);
    attn_kernel<<<NPAIR, 256, SMEM_A>>>(vs, ve, ved);

    // Both GEMMs in one launch: slots 0..16 (v_C splits), 17..18 (v_M splits)
    gemm_mma_kernel<<<dim3(NPAIR / 128, NSLOTS), 256, SMEM_MM>>>(ve, vs);

    // Fused reduce + bias + relu for both outputs
    reduce_relu_kernel<<<dim3(NPAIR * HD / 256, 2), 256>>>(bfwd, bmot, out);
}

// round 16
// speedup vs baseline: 1.2158x; 1.0929x over previous
#include <cuda_runtime.h>
#include <cuda_bf16.h>
#include <math.h>
#include <float.h>
#include <stdint.h>

// Problem constants
#define NPAIR 2048           // B*A
#define HD 128               // H
#define NTOK 256             // N
#define KTOP 16
#define NSPLIT1 17           // 2176 / 128
#define NSLOTS 19            // 17 (gemm1) + 2 (gemm2)

// Scratch (device globals; no allocations allowed)
__device__ float g_M[HD * HD];                    // norm * Wq @ Wk^T
__device__ float g_Wmod[HD * 2 * HD];             // [Wmot(:, :128) | Wv @ Wmot(:,128:)^T]
__device__ float g_X[NPAIR * 2 * HD];             // [vs | s_ve]
__device__ int   g_idx[NPAIR * KTOP];             // top-16 indices
__device__ float g_part[(size_t)NSLOTS * NPAIR * HD];  // split-K partials
// bf16 hi/lo weight splits
__device__ __nv_bfloat16 g_Wfh[HD * 2176];
__device__ __nv_bfloat16 g_Wfl[HD * 2176];
__device__ __nv_bfloat16 g_Wmh[HD * 256];
__device__ __nv_bfloat16 g_Wml[HD * 256];

__device__ __forceinline__ uint32_t smem_u32(const void* p) {
    uint32_t a;
    asm("{ .reg .u64 t; cvta.to.shared.u64 t, %1; cvt.u32.u64 %0, t; }" : "=r"(a) : "l"(p));
    return a;
}
#define MBAR_INIT(mb, c) asm volatile("mbarrier.init.shared.b64 [%0], %1;" \
    :: "r"((uint32_t)(mb)), "r"((uint32_t)(c)) : "memory")
#define MBAR_WAIT(mb, par) do { \
    uint32_t _mb = (uint32_t)(mb), _pa = (uint32_t)(par), _dn; \
    asm volatile("{\n\t.reg .pred p;\n\t" \
        "mbarrier.try_wait.parity.acquire.cta.shared::cta.b64 p, [%1], %2;\n\t" \
        "selp.b32 %0, 1, 0, p;\n\t}" : "=r"(_dn) : "r"(_mb), "r"(_pa) : "memory"); \
    if (!_dn) { \
        asm volatile("{\n\t.reg .pred P1;\n\tWL_%=:\n\t" \
            "mbarrier.try_wait.parity.acquire.cta.shared::cta.b64 P1, [%0], %1, 0x989680;\n\t" \
            "@P1 bra.uni WD_%=;\n\tbra.uni WL_%=;\n\tWD_%=:\n\t}" \
            :: "r"(_mb), "r"(_pa) : "memory"); \
    } } while (0)

// ---------------------------------------------------------------------------
// Kernel 0: build fused weight matrices. grid (128, 2), block 128
// ---------------------------------------------------------------------------
__global__ void prep_kernel(const float* __restrict__ Wq, const float* __restrict__ Wk,
                            const float* __restrict__ Wv, const float* __restrict__ Wmot) {
    __shared__ float srow[HD];
    int col = blockIdx.x;
    int t = threadIdx.x;
    if (blockIdx.y == 0) {
        srow[t] = Wk[col * HD + t];
        __syncthreads();
        const float* wq = Wq + t * HD;
        float acc = 0.f;
#pragma unroll 8
        for (int j = 0; j < HD; j++) acc += wq[j] * srow[j];
        g_M[t * HD + col] = acc * 0.08838834764831845f;  // 1/sqrt(128)
    } else {
        srow[t] = Wmot[col * 2 * HD + HD + t];
        __syncthreads();
        g_Wmod[col * 2 * HD + t] = Wmot[col * 2 * HD + t];
        const float* wv = Wv + t * HD;
        float acc = 0.f;
#pragma unroll 8
        for (int h = 0; h < HD; h++) acc += wv[h] * srow[h];
        g_Wmod[col * 2 * HD + HD + t] = acc;
    }
}

// ---------------------------------------------------------------------------
// Kernel 0b: split weights into bf16 hi/lo. Runs after prep (needs g_Wmod).
// ---------------------------------------------------------------------------
#define NWF (HD * 2176)
#define NWM (HD * 256)
__global__ void wconv_kernel(const float* __restrict__ Wfwd) {
    int i = blockIdx.x * 256 + threadIdx.x;
    if (i < NWF) {
        float w = Wfwd[i];
        __nv_bfloat16 h = __float2bfloat16_rn(w);
        g_Wfh[i] = h;
        g_Wfl[i] = __float2bfloat16_rn(w - __bfloat162float(h));
    } else if (i < NWF + NWM) {
        int j = i - NWF;
        float w = g_Wmod[j];
        __nv_bfloat16 h = __float2bfloat16_rn(w);
        g_Wmh[j] = h;
        g_Wml[j] = __float2bfloat16_rn(w - __bfloat162float(h));
    }
}

// ---------------------------------------------------------------------------
// Kernel 2: one-pass attention, cp.async.bulk pipeline, with qeff computed
// IN-KERNEL during the chunk-0 DMA wait (hides the old qeff kernel + gap).
// grid 2048, block 256, dyn smem 48 KB (3 x 16KB chunks of 32 rows).
// ---------------------------------------------------------------------------
__global__ __launch_bounds__(256, 4) void attn_kernel(const float* __restrict__ vs,
                                                      const float* __restrict__ ve,
                                                      const int* __restrict__ ved) {
    extern __shared__ float sve[];      // [3][4096] floats = 48 KB
    __shared__ float sc[NTOK];          // exp(compat)
    __shared__ float qs[HD];            // qeff row (computed in DMA shadow)
    __shared__ float svs[HD];           // vs row
    __shared__ float lred[8];
    __shared__ int sdead[NTOK];
    __shared__ uint64_t mbar[3];

    int tid = threadIdx.x;
    int lane = tid & 31, wid = tid >> 5;
    int p = blockIdx.x;

    sdead[tid] = ved[p * NTOK + tid];
    const char* src = (const char*)(ve + (size_t)p * NTOK * HD);
    uint32_t sbase = smem_u32(sve);

    if (tid < 3) MBAR_INIT(smem_u32(&mbar[tid]), 1);
    if (tid < HD) svs[tid] = vs[p * HD + tid];
    __syncthreads();

    auto issue = [&](int c) {
        int b = c % 3;
        uint32_t mb = smem_u32(&mbar[b]);
        asm volatile("mbarrier.arrive.expect_tx.shared.b64 _, [%0], %1;"
                     :: "r"(mb), "r"(16384u) : "memory");
        asm volatile("cp.async.bulk.shared::cta.global.mbarrier::complete_tx::bytes "
                     "[%0], [%1], %2, [%3];"
                     :: "r"(sbase + (uint32_t)b * 16384u), "l"(src + (size_t)c * 16384),
                        "r"(16384u), "r"(mb) : "memory");
    };
    if (tid == 0) { issue(0); issue(1); issue(2); }

    // qeff[t] = sum_i vs[i] * g_M[i][t] — runs under the chunk-0 DMA latency.
    if (tid < HD) {
        float a0 = 0.f, a1 = 0.f, a2 = 0.f, a3 = 0.f;
#pragma unroll 4
        for (int i = 0; i < HD; i += 4) {
            a0 += svs[i]     * g_M[i * HD + tid];
            a1 += svs[i + 1] * g_M[(i + 1) * HD + tid];
            a2 += svs[i + 2] * g_M[(i + 2) * HD + tid];
            a3 += svs[i + 3] * g_M[(i + 3) * HD + tid];
        }
        qs[tid] = (a0 + a1) + (a2 + a3);
    }
    __syncthreads();
    float4 q = *(const float4*)(qs + lane * 4);

    float l = 0.f;
    float4 acc = make_float4(0.f, 0.f, 0.f, 0.f);

    for (int c = 0; c < 8; c++) {
        int b = c % 3;
        MBAR_WAIT(smem_u32(&mbar[b]), (c / 3) & 1);

        const float* bb = sve + b * 4096 + (wid * 4) * 128 + lane * 4;
        float4 a0 = *(const float4*)(bb);
        float4 a1 = *(const float4*)(bb + 128);
        float4 a2 = *(const float4*)(bb + 256);
        float4 a3 = *(const float4*)(bb + 384);

        float c0 = a0.x * q.x + a0.y * q.y + a0.z * q.z + a0.w * q.w;
        float c1 = a1.x * q.x + a1.y * q.y + a1.z * q.z + a1.w * q.w;
        float c2 = a2.x * q.x + a2.y * q.y + a2.z * q.z + a2.w * q.w;
        float c3 = a3.x * q.x + a3.y * q.y + a3.z * q.z + a3.w * q.w;
#pragma unroll
        for (int o = 16; o > 0; o >>= 1) {
            c0 += __shfl_xor_sync(0xffffffffu, c0, o);
            c1 += __shfl_xor_sync(0xffffffffu, c1, o);
            c2 += __shfl_xor_sync(0xffffffffu, c2, o);
            c3 += __shfl_xor_sync(0xffffffffu, c3, o);
        }
        int r0 = c * 32 + wid * 4;
        float e0 = sdead[r0]     ? 0.f : expf(c0);
        float e1 = sdead[r0 + 1] ? 0.f : expf(c1);
        float e2 = sdead[r0 + 2] ? 0.f : expf(c2);
        float e3 = sdead[r0 + 3] ? 0.f : expf(c3);
        if (lane == 0) {
            sc[r0] = e0; sc[r0 + 1] = e1; sc[r0 + 2] = e2; sc[r0 + 3] = e3;
        }
        l += (e0 + e1) + (e2 + e3);
        acc.x += e0 * a0.x + e1 * a1.x + e2 * a2.x + e3 * a3.x;
        acc.y += e0 * a0.y + e1 * a1.y + e2 * a2.y + e3 * a3.y;
        acc.z += e0 * a0.z + e1 * a1.z + e2 * a2.z + e3 * a3.z;
        acc.w += e0 * a0.w + e1 * a1.w + e2 * a2.w + e3 * a3.w;

        __syncthreads();                  // all readers done with buffer b
        if (c < 5 && tid == 0) issue(c + 3);
    }

    // pipeline buffers dead: alias accumulator area into dynamic smem
    float* accsh = sve;                  // [8][132]
    if (lane == 0) lred[wid] = l;
    *(float4*)(accsh + wid * 132 + lane * 4) = acc;
    __syncthreads();

    float Lt = lred[0];
#pragma unroll
    for (int w = 1; w < 8; w++) Lt += lred[w];

    if (tid < HD) {
        float ssum = 0.f;
#pragma unroll
        for (int w = 0; w < 8; w++) ssum += accsh[w * 132 + tid];
        g_X[p * 2 * HD + tid] = svs[tid];
        g_X[p * 2 * HD + HD + tid] = (Lt > 0.f) ? ssum / Lt : 0.f;
    }
    __syncthreads();

    // top-16 on unnormalized e (monotone with score): stable desc, index asc.
    if (wid == 0) {
        float val[8];
#pragma unroll
        for (int j = 0; j < 8; j++) val[j] = sc[lane + (j << 5)];
        for (int k = 0; k < KTOP; k++) {
            float bv = val[0];
            int bj = 0;
#pragma unroll
            for (int j = 1; j < 8; j++)
                if (val[j] > bv) { bv = val[j]; bj = j; }  // strict > keeps lowest index
            int bi = (bj << 5) + lane;
#pragma unroll
            for (int o = 16; o > 0; o >>= 1) {
                float ov = __shfl_xor_sync(0xffffffffu, bv, o);
                int oi = __shfl_xor_sync(0xffffffffu, bi, o);
                if (ov > bv || (ov == bv && oi < bi)) { bv = ov; bi = oi; }
            }
            if (lane == 0) g_idx[p * KTOP + k] = bi;
            if ((bi & 31) == lane) val[bi >> 5] = -1.f;  // e >= 0
        }
    }
}

// ---------------------------------------------------------------------------
// Kernel 3: bf16 tensor-core GEMM (mma.sync m16n8k16), hi/lo fp32 recon.
// grid (16, 19): s<17 -> v_C split s; s>=17 -> v_M split s-17. Uniform work.
// W tiles via cp.async (overlap with A fetch+convert).
// Mainloop k-step-major: A hi+lo fragments loaded ONCE per k16 step, then
// per B-group (8 regs) do 3 MMA products -> 12 ldmatrix per step (was 18).
// ---------------------------------------------------------------------------
__global__ __launch_bounds__(256, 2) void gemm_mma_kernel(const float* __restrict__ ve,
                                                          const float* __restrict__ vs) {
    extern __shared__ char smg[];
    const uint32_t OFF_AH = 0, OFF_AL = 18432, OFF_WH = 36864, OFF_WL = 55296;
    uint32_t sb = smem_u32(smg);

    int tid = threadIdx.x;
    int lane = tid & 31, wid = tid >> 5;
    int br = blockIdx.x * 128;
    int s = blockIdx.y;
    int mode1 = (s >= NSPLIT1);
    int k0 = (mode1 ? (s - NSPLIT1) : s) * 128;
    int Kst = mode1 ? 256 : 2176;
    const __nv_bfloat16* Wh = mode1 ? g_Wmh : g_Wfh;
    const __nv_bfloat16* Wl = mode1 ? g_Wml : g_Wfl;

    int lr = tid >> 1, lh = tid & 1;
    const float* aptr;
    {
        int p = br + lr;
        if (!mode1) {
            aptr = (s == 0) ? vs + (size_t)p * HD
                            : ve + ((size_t)p * NTOK + g_idx[p * KTOP + s - 1]) * HD;
        } else {
            aptr = g_X + (size_t)p * 2 * HD + k0;
        }
    }
    const __nv_bfloat16* whp = Wh + (size_t)lr * Kst + k0;
    const __nv_bfloat16* wlp = Wl + (size_t)lr * Kst + k0;

    int wm = wid & 3;
    int wn = wid >> 2;
    uint32_t arow = (lane & 7) + ((lane >> 3) & 1) * 8;
    uint32_t akb  = (lane >> 4) * 16;
    uint32_t nrow = ((lane >> 4) & 1) * 8 + (lane & 7);
    uint32_t bkb  = ((lane >> 3) & 1) * 16;

    float acc[2][8][4];
#pragma unroll
    for (int i = 0; i < 2; i++)
#pragma unroll
        for (int j = 0; j < 8; j++)
#pragma unroll
            for (int v = 0; v < 4; v++) acc[i][j][v] = 0.f;

    for (int kk = 0; kk < 2; kk++) {
        {
            // Issue W tile fills first via cp.async (overlaps with A below)
            uint32_t dWh = sb + OFF_WH + lr * 144 + lh * 64;
            uint32_t dWl = sb + OFF_WL + lr * 144 + lh * 64;
            const char* gWh = (const char*)(whp + kk * 64 + lh * 32);
            const char* gWl = (const char*)(wlp + kk * 64 + lh * 32);
#pragma unroll
            for (int j = 0; j < 4; j++) {
                asm volatile("cp.async.cg.shared.global [%0], [%1], 16;"
                             :: "r"(dWh + j * 16), "l"(gWh + j * 16));
                asm volatile("cp.async.cg.shared.global [%0], [%1], 16;"
                             :: "r"(dWl + j * 16), "l"(gWl + j * 16));
            }
            asm volatile("cp.async.commit_group;" ::: "memory");

            // A: 32 fp32 -> bf16 hi/lo
            const float4* a4 = (const float4*)(aptr + kk * 64 + lh * 32);
            char* dAh = smg + OFF_AH + lr * 144 + lh * 64;
            char* dAl = smg + OFF_AL + lr * 144 + lh * 64;
#pragma unroll
            for (int j = 0; j < 8; j++) {
                float4 f = a4[j];
                __nv_bfloat162 h0 = __floats2bfloat162_rn(f.x, f.y);
                __nv_bfloat162 h1 = __floats2bfloat162_rn(f.z, f.w);
                float2 r0 = __bfloat1622float2(h0);
                float2 r1 = __bfloat1622float2(h1);
                __nv_bfloat162 l0 = __floats2bfloat162_rn(f.x - r0.x, f.y - r0.y);
                __nv_bfloat162 l1 = __floats2bfloat162_rn(f.z - r1.x, f.w - r1.y);
                *(uint2*)(dAh + j * 8) = make_uint2(*(uint32_t*)&h0, *(uint32_t*)&h1);
                *(uint2*)(dAl + j * 8) = make_uint2(*(uint32_t*)&l0, *(uint32_t*)&l1);
            }
            asm volatile("cp.async.wait_group 0;" ::: "memory");
        }
        __syncthreads();

        uint32_t Abh = sb + OFF_AH + (wm * 32 + arow) * 144 + akb;
        uint32_t Abl = sb + OFF_AL + (wm * 32 + arow) * 144 + akb;
        uint32_t Wbh = sb + OFF_WH + (wn * 64 + nrow) * 144 + bkb;
        uint32_t Wbl = sb + OFF_WL + (wn * 64 + nrow) * 144 + bkb;

#pragma unroll
        for (int ks = 0; ks < 4; ks++) {
            // A fragments (hi + lo), loaded once per k-step
            uint32_t ah[2][4], al[2][4];
#pragma unroll
            for (int mt = 0; mt < 2; mt++) {
                asm volatile("ldmatrix.sync.aligned.m8n8.x4.shared.b16 {%0,%1,%2,%3}, [%4];"
                             : "=r"(ah[mt][0]), "=r"(ah[mt][1]), "=r"(ah[mt][2]), "=r"(ah[mt][3])
                             : "r"(Abh + mt * 16 * 144 + ks * 32));
                asm volatile("ldmatrix.sync.aligned.m8n8.x4.shared.b16 {%0,%1,%2,%3}, [%4];"
                             : "=r"(al[mt][0]), "=r"(al[mt][1]), "=r"(al[mt][2]), "=r"(al[mt][3])
                             : "r"(Abl + mt * 16 * 144 + ks * 32));
            }
            // B groups: 2 nt columns each; hi+lo fragments; 3 products
#pragma unroll
            for (int g = 0; g < 4; g++) {
                uint32_t wh[4], wl[4];
                asm volatile("ldmatrix.sync.aligned.m8n8.x4.shared.b16 {%0,%1,%2,%3}, [%4];"
                             : "=r"(wh[0]), "=r"(wh[1]), "=r"(wh[2]), "=r"(wh[3])
                             : "r"(Wbh + g * 16 * 144 + ks * 32));
                asm volatile("ldmatrix.sync.aligned.m8n8.x4.shared.b16 {%0,%1,%2,%3}, [%4];"
                             : "=r"(wl[0]), "=r"(wl[1]), "=r"(wl[2]), "=r"(wl[3])
                             : "r"(Wbl + g * 16 * 144 + ks * 32));
#pragma unroll
                for (int mt = 0; mt < 2; mt++) {
#pragma unroll
                    for (int sub = 0; sub < 2; sub++) {
                        int nt = g * 2 + sub;
                        asm volatile(
                            "mma.sync.aligned.m16n8k16.row.col.f32.bf16.bf16.f32 "
                            "{%0,%1,%2,%3}, {%4,%5,%6,%7}, {%8,%9}, {%0,%1,%2,%3};"
                            : "+f"(acc[mt][nt][0]), "+f"(acc[mt][nt][1]),
                              "+f"(acc[mt][nt][2]), "+f"(acc[mt][nt][3])
                            : "r"(ah[mt][0]), "r"(ah[mt][1]), "r"(ah[mt][2]), "r"(ah[mt][3]),
                              "r"(wh[sub * 2]), "r"(wh[sub * 2 + 1]));
                        asm volatile(
                            "mma.sync.aligned.m16n8k16.row.col.f32.bf16.bf16.f32 "
                            "{%0,%1,%2,%3}, {%4,%5,%6,%7}, {%8,%9}, {%0,%1,%2,%3};"
                            : "+f"(acc[mt][nt][0]), "+f"(acc[mt][nt][1]),
                              "+f"(acc[mt][nt][2]), "+f"(acc[mt][nt][3])
                            : "r"(ah[mt][0]), "r"(ah[mt][1]), "r"(ah[mt][2]), "r"(ah[mt][3]),
                              "r"(wl[sub * 2]), "r"(wl[sub * 2 + 1]));
                        asm volatile(
                            "mma.sync.aligned.m16n8k16.row.col.f32.bf16.bf16.f32 "
                            "{%0,%1,%2,%3}, {%4,%5,%6,%7}, {%8,%9}, {%0,%1,%2,%3};"
                            : "+f"(acc[mt][nt][0]), "+f"(acc[mt][nt][1]),
                              "+f"(acc[mt][nt][2]), "+f"(acc[mt][nt][3])
                            : "r"(al[mt][0]), "r"(al[mt][1]), "r"(al[mt][2]), "r"(al[mt][3]),
                              "r"(wh[sub * 2]), "r"(wh[sub * 2 + 1]));
                    }
                }
            }
        }
        __syncthreads();
    }

    float* pout = g_part + (size_t)s * NPAIR * HD + (size_t)br * HD;
#pragma unroll
    for (int mt = 0; mt < 2; mt++) {
        int row0 = wm * 32 + mt * 16 + (lane >> 2);
#pragma unroll
        for (int nt = 0; nt < 8; nt++) {
            int col = wn * 64 + nt * 8 + (lane & 3) * 2;
            *(float2*)(pout + (size_t)row0 * HD + col) =
                make_float2(acc[mt][nt][0], acc[mt][nt][1]);
            *(float2*)(pout + (size_t)(row0 + 8) * HD + col) =
                make_float2(acc[mt][nt][2], acc[mt][nt][3]);
        }
    }
}

// Fused reduce: y==0 -> v_C (17 splits, slots 0..16); y==1 -> v_M (slots 17,18)
__global__ void reduce_relu_kernel(const float* __restrict__ bfwd,
                                   const float* __restrict__ bmot,
                                   float* __restrict__ out) {
    int idx = blockIdx.x * 256 + threadIdx.x;
    if (blockIdx.y == 0) {
        float s = 0.f;
#pragma unroll
        for (int sp = 0; sp < NSPLIT1; sp++) s += g_part[(size_t)sp * NPAIR * HD + idx];
        out[idx] = fmaxf(s + bfwd[idx & (HD - 1)], 0.f);
    } else {
        float s = g_part[(size_t)17 * NPAIR * HD + idx] +
                  g_part[(size_t)18 * NPAIR * HD + idx];
        out[NPAIR * HD + idx] = fmaxf(s + bmot[idx & (HD - 1)], 0.f);
    }
}

// ---------------------------------------------------------------------------
extern "C" void kernel_launch(void* const* d_in, const int* in_sizes, int n_in,
                              void* d_out, int out_size) {
    const float* vs   = (const float*)d_in[0];
    const float* ve   = (const float*)d_in[1];
    const int*   ved  = (const int*)d_in[2];
    const float* Wq   = (const float*)d_in[3];
    const float* Wk   = (const float*)d_in[4];
    const float* Wv   = (const float*)d_in[5];
    const float* Wmot = (const float*)d_in[6];
    const float* bmot = (const float*)d_in[7];
    const float* Wfwd = (const float*)d_in[8];
    const float* bfwd = (const float*)d_in[9];
    float* out = (float*)d_out;  // [v_C_final (2048*128) | v_M_final (2048*128)]

    const int SMEM_A  = 3 * 4096 * 4;   // 48 KB attn pipeline
    const int SMEM_MM = 73728;          // 4 x 18432 B bf16 tiles
    cudaFuncSetAttribute(attn_kernel, cudaFuncAttributeMaxDynamicSharedMemorySize, SMEM_A);
    cudaFuncSetAttribute(gemm_mma_kernel, cudaFuncAttributeMaxDynamicSharedMemorySize, SMEM_MM);

    // 5 launches (qeff folded into attn)
    prep_kernel<<<dim3(128, 2), 128>>>(Wq, Wk, Wv, Wmot);
    wconv_kernel<<<(NWF + NWM + 255) / 256, 256>>>(Wfwd);
    attn_kernel<<<NPAIR, 256, SMEM_A>>>(vs, ve, ved);

    // Both GEMMs in one launch: slots 0..16 (v_C splits), 17..18 (v_M splits)
    gemm_mma_kernel<<<dim3(NPAIR / 128, NSLOTS), 256, SMEM_MM>>>(ve, vs);

    // Fused reduce + bias + relu for both outputs
    reduce_relu_kernel<<<dim3(NPAIR * HD / 256, 2), 256>>>(bfwd, bmot, out);
}